// round 2
// baseline (speedup 1.0000x reference)
#include <cuda_runtime.h>

// Problem constants
#define BATCH 8
#define SEQ   2048
#define DIM   512
#define MROWS (BATCH*SEQ)   // 16384
#define NPROJ (3*DIM)       // 1536
#define N2    (2*DIM)       // 1024

// GEMM tiling
#define BM 128
#define BN 128
#define BK 16

// Scratch (static device globals — no allocation allowed)
__device__ __align__(16) float g_xT[DIM * MROWS];     // x transposed [K=512][M=16384]
__device__ __align__(16) float g_WT[DIM * NPROJ];     // [Wq|Wk|Wv]^T packed [512][1536]
__device__ __align__(16) float g_Y [MROWS * NPROJ];   // raw q|k|v projections [16384][1536]
__device__ __align__(16) float g_C [MROWS * N2];      // interleaved {kw*v, kw} [16384][1024]
__device__ __align__(16) float g_dw[BATCH * SEQ * SEQ];// exp(-alpha*log2N*dis) [8][2048][2048]

// ---------------------------------------------------------------------------
// Transpose x: g_xT[k][m] = x[m][k]   (m=16384 rows, k=512 cols)
// ---------------------------------------------------------------------------
__global__ void transpose_x_kernel(const float* __restrict__ in) {
    __shared__ float tile[32][33];
    int c0 = blockIdx.x * 32;   // k
    int r0 = blockIdx.y * 32;   // m
    #pragma unroll
    for (int rr = threadIdx.y; rr < 32; rr += 8)
        tile[rr][threadIdx.x] = in[(r0 + rr) * DIM + c0 + threadIdx.x];
    __syncthreads();
    #pragma unroll
    for (int rr = threadIdx.y; rr < 32; rr += 8)
        g_xT[(c0 + rr) * MROWS + r0 + threadIdx.x] = tile[threadIdx.x][rr];
}

// Transpose one 512x512 W into g_WT at column offset ooff: g_WT[k][ooff+o] = W[o][k]
__global__ void transpose_w_kernel(const float* __restrict__ in, int ooff) {
    __shared__ float tile[32][33];
    int c0 = blockIdx.x * 32;   // k
    int r0 = blockIdx.y * 32;   // o
    #pragma unroll
    for (int rr = threadIdx.y; rr < 32; rr += 8)
        tile[rr][threadIdx.x] = in[(r0 + rr) * DIM + c0 + threadIdx.x];
    __syncthreads();
    #pragma unroll
    for (int rr = threadIdx.y; rr < 32; rr += 8)
        g_WT[(c0 + rr) * NPROJ + ooff + r0 + threadIdx.x] = tile[threadIdx.x][rr];
}

// ---------------------------------------------------------------------------
// dw = exp(-alpha * log2(N) * dis), elementwise, float4-vectorized
// ---------------------------------------------------------------------------
__global__ void dw_kernel(const float* __restrict__ dis, const float* __restrict__ alpha) {
    int i = blockIdx.x * blockDim.x + threadIdx.x;   // over float4s
    float c = -alpha[0] * 11.0f;                     // log2(2048) = 11 exactly
    float4 d4 = ((const float4*)dis)[i];
    float4 o;
    o.x = __expf(c * d4.x);
    o.y = __expf(c * d4.y);
    o.z = __expf(c * d4.z);
    o.w = __expf(c * d4.w);
    ((float4*)g_dw)[i] = o;
}

// ---------------------------------------------------------------------------
// Build C: C[m][2d] = exp(k)*v, C[m][2d+1] = exp(k)
// ---------------------------------------------------------------------------
__global__ void buildc_kernel() {
    int i = blockIdx.x * blockDim.x + threadIdx.x;   // over MROWS*DIM/4
    int m  = i >> 7;          // /128
    int d0 = (i & 127) << 2;  // 4 features
    const float* yrow = g_Y + m * NPROJ;
    float4 k4 = *(const float4*)&yrow[DIM   + d0];
    float4 v4 = *(const float4*)&yrow[2*DIM + d0];
    float kw0 = __expf(k4.x), kw1 = __expf(k4.y);
    float kw2 = __expf(k4.z), kw3 = __expf(k4.w);
    float4 a = make_float4(kw0 * v4.x, kw0, kw1 * v4.y, kw1);
    float4 b = make_float4(kw2 * v4.z, kw2, kw3 * v4.w, kw3);
    float* crow = g_C + m * N2 + 2 * d0;
    *(float4*)&crow[0] = a;
    *(float4*)&crow[4] = b;
}

// ---------------------------------------------------------------------------
// Projection GEMM (TN): Y[m][o] = sum_k g_xT[k][m] * g_WT[k][o]
// M=16384, N=1536, K=512
// ---------------------------------------------------------------------------
__global__ void __launch_bounds__(256, 2) proj_gemm_kernel() {
    __shared__ float As[BK][BM];
    __shared__ float Bs[BK][BN];
    const int lda = MROWS, ldb = NPROJ, K = DIM;
    int m0 = blockIdx.y * BM;
    int n0 = blockIdx.x * BN;
    int tid = threadIdx.x;
    int tx = tid & 15, ty = tid >> 4;
    int lr = tid >> 5;          // 0..7 (k row)
    int lc = (tid & 31) << 2;   // 0..124 (float4 col)

    float acc[8][8];
    #pragma unroll
    for (int i = 0; i < 8; i++)
        #pragma unroll
        for (int j = 0; j < 8; j++) acc[i][j] = 0.f;

    for (int k0 = 0; k0 < K; k0 += BK) {
        #pragma unroll
        for (int r = 0; r < 2; r++) {
            int kk = lr + r * 8;
            *(float4*)&As[kk][lc] = *(const float4*)&g_xT[(k0 + kk) * lda + m0 + lc];
            *(float4*)&Bs[kk][lc] = *(const float4*)&g_WT[(k0 + kk) * ldb + n0 + lc];
        }
        __syncthreads();
        #pragma unroll
        for (int kk = 0; kk < BK; kk++) {
            float ar[8], br[8];
            *(float4*)&ar[0] = *(float4*)&As[kk][ty * 4];
            *(float4*)&ar[4] = *(float4*)&As[kk][64 + ty * 4];
            *(float4*)&br[0] = *(float4*)&Bs[kk][tx * 4];
            *(float4*)&br[4] = *(float4*)&Bs[kk][64 + tx * 4];
            #pragma unroll
            for (int i = 0; i < 8; i++)
                #pragma unroll
                for (int j = 0; j < 8; j++)
                    acc[i][j] += ar[i] * br[j];
        }
        __syncthreads();
    }
    // write raw projections
    #pragma unroll
    for (int i = 0; i < 8; i++) {
        int m = m0 + ((i < 4) ? (ty * 4 + i) : (64 + ty * 4 + i - 4));
        float* yrow = g_Y + m * NPROJ + n0;
        *(float4*)&yrow[tx * 4]      = make_float4(acc[i][0], acc[i][1], acc[i][2], acc[i][3]);
        *(float4*)&yrow[64 + tx * 4] = make_float4(acc[i][4], acc[i][5], acc[i][6], acc[i][7]);
    }
}

// ---------------------------------------------------------------------------
// Main GEMM (TN, batched): for batch b:
//   W12[j][n] = sum_i g_dw[b][i][j] * g_C[b][i][n]   (n over 1024 = {d,pair})
// Fused epilogue: out[b][j][d] = sigmoid(q[b][j][d]) * W1/W2
// ---------------------------------------------------------------------------
__global__ void __launch_bounds__(256, 2) main_gemm_kernel(float* __restrict__ out) {
    __shared__ float As[BK][BM];
    __shared__ float Bs[BK][BN];
    int b = blockIdx.z;
    const float* A    = g_dw + b * SEQ * SEQ;   // [k=i][m=j], lda=SEQ
    const float* Bmat = g_C  + b * SEQ * N2;    // [k=i][n],   ldb=N2
    const int lda = SEQ, ldb = N2, K = SEQ;
    int m0 = blockIdx.y * BM;
    int n0 = blockIdx.x * BN;
    int tid = threadIdx.x;
    int tx = tid & 15, ty = tid >> 4;
    int lr = tid >> 5;
    int lc = (tid & 31) << 2;

    float acc[8][8];
    #pragma unroll
    for (int i = 0; i < 8; i++)
        #pragma unroll
        for (int j = 0; j < 8; j++) acc[i][j] = 0.f;

    for (int k0 = 0; k0 < K; k0 += BK) {
        #pragma unroll
        for (int r = 0; r < 2; r++) {
            int kk = lr + r * 8;
            *(float4*)&As[kk][lc] = *(const float4*)&A[(k0 + kk) * lda + m0 + lc];
            *(float4*)&Bs[kk][lc] = *(const float4*)&Bmat[(k0 + kk) * ldb + n0 + lc];
        }
        __syncthreads();
        #pragma unroll
        for (int kk = 0; kk < BK; kk++) {
            float ar[8], br[8];
            *(float4*)&ar[0] = *(float4*)&As[kk][ty * 4];
            *(float4*)&ar[4] = *(float4*)&As[kk][64 + ty * 4];
            *(float4*)&br[0] = *(float4*)&Bs[kk][tx * 4];
            *(float4*)&br[4] = *(float4*)&Bs[kk][64 + tx * 4];
            #pragma unroll
            for (int i = 0; i < 8; i++)
                #pragma unroll
                for (int j = 0; j < 8; j++)
                    acc[i][j] += ar[i] * br[j];
        }
        __syncthreads();
    }

    // Fused epilogue: columns come in (w1, w2) pairs; d = col/2
    #pragma unroll
    for (int i = 0; i < 8; i++) {
        int m = m0 + ((i < 4) ? (ty * 4 + i) : (64 + ty * 4 + i - 4));   // j
        int row = b * SEQ + m;
        const float* qrow = g_Y + row * NPROJ;  // q part is cols [0,512)
        float* orow = out + row * DIM;

        int d0 = (n0 + tx * 4) >> 1;            // even
        float2 q0 = *(const float2*)&qrow[d0];
        float s00 = __fdividef(1.f, 1.f + __expf(-q0.x));
        float s01 = __fdividef(1.f, 1.f + __expf(-q0.y));
        *(float2*)&orow[d0] = make_float2(s00 * __fdividef(acc[i][0], acc[i][1]),
                                          s01 * __fdividef(acc[i][2], acc[i][3]));

        int d1 = (n0 + 64 + tx * 4) >> 1;       // even
        float2 q1 = *(const float2*)&qrow[d1];
        float s10 = __fdividef(1.f, 1.f + __expf(-q1.x));
        float s11 = __fdividef(1.f, 1.f + __expf(-q1.y));
        *(float2*)&orow[d1] = make_float2(s10 * __fdividef(acc[i][4], acc[i][5]),
                                          s11 * __fdividef(acc[i][6], acc[i][7]));
    }
}

// ---------------------------------------------------------------------------
extern "C" void kernel_launch(void* const* d_in, const int* in_sizes, int n_in,
                              void* d_out, int out_size) {
    const float* x     = (const float*)d_in[0];
    const float* dis   = (const float*)d_in[1];
    const float* Wq    = (const float*)d_in[2];
    const float* Wk    = (const float*)d_in[3];
    const float* Wv    = (const float*)d_in[4];
    const float* alpha = (const float*)d_in[5];
    float* out = (float*)d_out;

    dim3 tt(32, 8);

    // 1) transposes / packing
    transpose_x_kernel<<<dim3(DIM / 32, MROWS / 32), tt>>>(x);
    transpose_w_kernel<<<dim3(DIM / 32, DIM / 32), tt>>>(Wq, 0);
    transpose_w_kernel<<<dim3(DIM / 32, DIM / 32), tt>>>(Wk, DIM);
    transpose_w_kernel<<<dim3(DIM / 32, DIM / 32), tt>>>(Wv, 2 * DIM);

    // 2) dis_weight = exp(-alpha*11*dis)
    dw_kernel<<<(BATCH * SEQ * SEQ / 4) / 256, 256>>>(dis, alpha);

    // 3) projections: Y = x @ [Wq|Wk|Wv]^T
    proj_gemm_kernel<<<dim3(NPROJ / BN, MROWS / BM), 256>>>();

    // 4) C = interleave(exp(k)*v, exp(k))
    buildc_kernel<<<(MROWS * DIM / 4) / 256, 256>>>();

    // 5) batched main GEMM with fused sigmoid(q)*W1/W2 epilogue
    main_gemm_kernel<<<dim3(N2 / BN, SEQ / BM, BATCH), 256>>>(out);
}

// round 10
// speedup vs baseline: 1.3626x; 1.3626x over previous
#include <cuda_runtime.h>
#include <mma.h>
#include <cstdint>

using namespace nvcuda;

// Problem constants
#define BATCH 8
#define SEQ   2048
#define DIM   512
#define MROWS (BATCH*SEQ)   // 16384
#define NPROJ (3*DIM)       // 1536
#define N2    1024          // interleaved (w1,w2) feature dim

// WMMA GEMM tiling
#define BM 128
#define BN 128
#define BK 32
#define LDS_PAD 36          // 32 + 4 floats, 16B-aligned rows
#define TILE_FLOATS (BM*LDS_PAD)            // 4608
#define STAGE_FLOATS (2*TILE_FLOATS)        // A + B
#define SMEM_BYTES (2*STAGE_FLOATS*4)       // 2 stages = 73728

// Scratch (static device globals — no allocation allowed)
__device__ __align__(16) float g_xtf [(size_t)MROWS * DIM];     // x as tf32
__device__ __align__(16) float g_Wtf [(size_t)NPROJ * DIM];     // [Wq;Wk;Wv] as tf32
__device__ __align__(16) float g_Y   [(size_t)MROWS * NPROJ];   // q|k|v projections (fp32)
__device__ __align__(16) float g_dwA [(size_t)BATCH * SEQ * SEQ];   // dw^T as tf32 [b][j][i]
__device__ __align__(16) float g_CT  [(size_t)BATCH * N2 * SEQ];    // [b][n][i] tf32
__device__ __align__(16) float g_W12 [(size_t)MROWS * N2];      // GEMM result (fp32)

// ---------------------------------------------------------------------------
// helpers
// ---------------------------------------------------------------------------
__device__ __forceinline__ uint32_t smem_u32(const void* p) {
    uint32_t a;
    asm("{ .reg .u64 t; cvta.to.shared.u64 t, %1; cvt.u32.u64 %0, t; }" : "=r"(a) : "l"(p));
    return a;
}
__device__ __forceinline__ float to_tf32f(float x) {
    uint32_t u; asm("cvt.rna.tf32.f32 %0, %1;" : "=r"(u) : "f"(x));
    return __uint_as_float(u);
}
__device__ __forceinline__ void cp16(float* dst_smem, const float* src) {
    uint32_t d = smem_u32(dst_smem);
    asm volatile("cp.async.cg.shared.global [%0], [%1], 16;" :: "r"(d), "l"(src));
}
#define CP_COMMIT() asm volatile("cp.async.commit_group;" ::: "memory")
#define CP_WAIT(n)  asm volatile("cp.async.wait_group %0;" :: "n"(n) : "memory")

// ---------------------------------------------------------------------------
// tf32 convert-copy (elementwise, float4)
// ---------------------------------------------------------------------------
__global__ void cvt_kernel(const float* __restrict__ in, float* __restrict__ out) {
    size_t i = (size_t)blockIdx.x * blockDim.x + threadIdx.x;
    float4 v = ((const float4*)in)[i];
    float4 o;
    o.x = to_tf32f(v.x); o.y = to_tf32f(v.y);
    o.z = to_tf32f(v.z); o.w = to_tf32f(v.w);
    ((float4*)out)[i] = o;
}

// ---------------------------------------------------------------------------
// dwA[b][j][i] = tf32(exp(-alpha*11*dis[b][i][j]))  — transpose + exp
// grid (64, 64, 8), block (32, 8)
// ---------------------------------------------------------------------------
__global__ void dwA_kernel(const float* __restrict__ dis, const float* __restrict__ alpha) {
    __shared__ float tile[32][33];
    int i0 = blockIdx.x * 32, j0 = blockIdx.y * 32, b = blockIdx.z;
    float c = -alpha[0] * 11.0f;   // log2(2048) = 11 exactly
    const float* src = dis + ((size_t)b * SEQ + i0) * SEQ + j0;
    #pragma unroll
    for (int rr = threadIdx.y; rr < 32; rr += 8)
        tile[rr][threadIdx.x] = __expf(c * src[(size_t)rr * SEQ + threadIdx.x]);
    __syncthreads();
    float* dst = g_dwA + ((size_t)b * SEQ + j0) * SEQ + i0;
    #pragma unroll
    for (int rr = threadIdx.y; rr < 32; rr += 8)
        dst[(size_t)rr * SEQ + threadIdx.x] = to_tf32f(tile[threadIdx.x][rr]);
}

// ---------------------------------------------------------------------------
// CT[b][n][i]: n=2d -> tf32(exp(k)*v), n=2d+1 -> tf32(exp(k))
// block covers 32 i x 64 d  ->  128 n-rows x 32 i.  grid (64, 8, 8), 256 thr
// ---------------------------------------------------------------------------
__global__ void cT_kernel() {
    __shared__ float ks[32][65];   // exp(k)
    __shared__ float vs[32][65];
    int i0 = blockIdx.x * 32, d0 = blockIdx.y * 64, b = blockIdx.z;
    int tid = threadIdx.x;
    // fill: 32 i x 64 d = 2048 elems / 256 thr = 8 each
    #pragma unroll
    for (int u = tid; u < 32 * 64; u += 256) {
        int ii = u >> 6, dd = u & 63;
        const float* yrow = g_Y + ((size_t)b * SEQ + i0 + ii) * NPROJ;
        ks[ii][dd] = __expf(yrow[DIM + d0 + dd]);
        vs[ii][dd] = yrow[2 * DIM + d0 + dd];
    }
    __syncthreads();
    // write: 128 n-rows x 8 float4 = 1024 float4 / 256 thr = 4 each
    #pragma unroll
    for (int u = tid; u < 128 * 8; u += 256) {
        int n = u >> 3, i4 = (u & 7) * 4;
        int d = n >> 1, p = n & 1;
        float4 o;
        float k0 = ks[i4+0][d], k1 = ks[i4+1][d], k2 = ks[i4+2][d], k3 = ks[i4+3][d];
        if (p) {
            o.x = to_tf32f(k0); o.y = to_tf32f(k1); o.z = to_tf32f(k2); o.w = to_tf32f(k3);
        } else {
            o.x = to_tf32f(k0 * vs[i4+0][d]); o.y = to_tf32f(k1 * vs[i4+1][d]);
            o.z = to_tf32f(k2 * vs[i4+2][d]); o.w = to_tf32f(k3 * vs[i4+3][d]);
        }
        *(float4*)&g_CT[((size_t)b * N2 + d0 * 2 + n) * SEQ + i0 + i4] = o;
    }
}

// ---------------------------------------------------------------------------
// Generic WMMA tf32 GEMM (row.col): C[m][n] = sum_k A[m][k] * B[n][k]
// A row-major (lda), B "col-major" fragment = row-major [n][k] (ldb).
// 128x128x32 tiles, cp.async double-buffered, 256 threads (8 warps, 64x32 each)
// ---------------------------------------------------------------------------
__global__ void __launch_bounds__(256, 1)
wmma_gemm_kernel(const float* __restrict__ A, const float* __restrict__ B,
                 float* __restrict__ C, int lda, int ldb, int ldc, int K,
                 size_t sA, size_t sB, size_t sC) {
    extern __shared__ float smem[];
    float* As = smem;                       // 2 stages x 4608
    float* Bs = smem + 2 * TILE_FLOATS;     // 2 stages x 4608

    A += (size_t)blockIdx.z * sA;
    B += (size_t)blockIdx.z * sB;
    C += (size_t)blockIdx.z * sC;

    int m0 = blockIdx.y * BM, n0 = blockIdx.x * BN;
    int tid = threadIdx.x;
    int wid = tid >> 5;
    int warp_m = wid & 1;    // 2 along M (64 rows each)
    int warp_n = wid >> 1;   // 4 along N (32 cols each)

    wmma::fragment<wmma::accumulator, 16, 16, 8, float> c[4][2];
    #pragma unroll
    for (int mi = 0; mi < 4; mi++)
        #pragma unroll
        for (int ni = 0; ni < 2; ni++) wmma::fill_fragment(c[mi][ni], 0.0f);

    const int KT = K / BK;

    // tile loader: 128 rows x 8 float4 per operand
    auto load_stage = [&](int kt, int s) {
        const float* Ag = A + (size_t)m0 * lda + kt * BK;
        const float* Bg = B + (size_t)n0 * ldb + kt * BK;
        float* Ad = As + s * TILE_FLOATS;
        float* Bd = Bs + s * TILE_FLOATS;
        #pragma unroll
        for (int it = 0; it < 4; it++) {
            int idx = tid + it * 256;
            int row = idx >> 3, c4 = (idx & 7) * 4;
            cp16(Ad + row * LDS_PAD + c4, Ag + (size_t)row * lda + c4);
            cp16(Bd + row * LDS_PAD + c4, Bg + (size_t)row * ldb + c4);
        }
    };

    load_stage(0, 0);
    CP_COMMIT();

    for (int kt = 0; kt < KT; kt++) {
        int s = kt & 1;
        if (kt + 1 < KT) {
            load_stage(kt + 1, s ^ 1);
            CP_COMMIT();
            CP_WAIT(1);
        } else {
            CP_WAIT(0);
        }
        __syncthreads();

        const float* Abase = As + s * TILE_FLOATS + (warp_m * 64) * LDS_PAD;
        const float* Bbase = Bs + s * TILE_FLOATS + (warp_n * 32) * LDS_PAD;
        #pragma unroll
        for (int ks = 0; ks < BK / 8; ks++) {
            wmma::fragment<wmma::matrix_a, 16, 16, 8, wmma::precision::tf32, wmma::row_major> a[4];
            wmma::fragment<wmma::matrix_b, 16, 16, 8, wmma::precision::tf32, wmma::col_major> bfr[2];
            #pragma unroll
            for (int mi = 0; mi < 4; mi++)
                wmma::load_matrix_sync(a[mi], Abase + mi * 16 * LDS_PAD + ks * 8, LDS_PAD);
            #pragma unroll
            for (int ni = 0; ni < 2; ni++)
                wmma::load_matrix_sync(bfr[ni], Bbase + ni * 16 * LDS_PAD + ks * 8, LDS_PAD);
            #pragma unroll
            for (int mi = 0; mi < 4; mi++)
                #pragma unroll
                for (int ni = 0; ni < 2; ni++)
                    wmma::mma_sync(c[mi][ni], a[mi], bfr[ni], c[mi][ni]);
        }
        __syncthreads();
    }

    #pragma unroll
    for (int mi = 0; mi < 4; mi++)
        #pragma unroll
        for (int ni = 0; ni < 2; ni++) {
            int m = m0 + warp_m * 64 + mi * 16;
            int n = n0 + warp_n * 32 + ni * 16;
            wmma::store_matrix_sync(C + (size_t)m * ldc + n, c[mi][ni], ldc, wmma::mem_row_major);
        }
}

// ---------------------------------------------------------------------------
// Epilogue: out[row][d] = sigmoid(q[row][d]) * W12[row][2d] / W12[row][2d+1]
// one float4 of output per thread-iter; 16384*512/4 = 2,097,152 float4
// ---------------------------------------------------------------------------
__global__ void epilogue_kernel(float* __restrict__ out) {
    size_t idx = (size_t)blockIdx.x * blockDim.x + threadIdx.x;
    int row = (int)(idx >> 7);          // 128 float4 per row
    int d0  = (int)(idx & 127) * 4;
    const float* qp = g_Y + (size_t)row * NPROJ + d0;
    const float* wp = g_W12 + (size_t)row * N2 + 2 * d0;
    float4 q  = *(const float4*)qp;
    float4 wa = *(const float4*)(wp);       // pairs (d0), (d0+1)
    float4 wb = *(const float4*)(wp + 4);   // pairs (d0+2), (d0+3)
    float4 o;
    o.x = __fdividef(1.f, 1.f + __expf(-q.x)) * __fdividef(wa.x, wa.y);
    o.y = __fdividef(1.f, 1.f + __expf(-q.y)) * __fdividef(wa.z, wa.w);
    o.z = __fdividef(1.f, 1.f + __expf(-q.z)) * __fdividef(wb.x, wb.y);
    o.w = __fdividef(1.f, 1.f + __expf(-q.w)) * __fdividef(wb.z, wb.w);
    *(float4*)(out + (size_t)row * DIM + d0) = o;
}

// ---------------------------------------------------------------------------
extern "C" void kernel_launch(void* const* d_in, const int* in_sizes, int n_in,
                              void* d_out, int out_size) {
    const float* x     = (const float*)d_in[0];
    const float* dis   = (const float*)d_in[1];
    const float* Wq    = (const float*)d_in[2];
    const float* Wk    = (const float*)d_in[3];
    const float* Wv    = (const float*)d_in[4];
    const float* alpha = (const float*)d_in[5];
    float* out = (float*)d_out;

    cudaFuncSetAttribute(wmma_gemm_kernel, cudaFuncAttributeMaxDynamicSharedMemorySize, SMEM_BYTES);

    float* d_xtf;  cudaGetSymbolAddress((void**)&d_xtf,  g_xtf);
    float* d_Wtf;  cudaGetSymbolAddress((void**)&d_Wtf,  g_Wtf);
    float* d_Y;    cudaGetSymbolAddress((void**)&d_Y,    g_Y);
    float* d_dwA;  cudaGetSymbolAddress((void**)&d_dwA,  g_dwA);
    float* d_CT;   cudaGetSymbolAddress((void**)&d_CT,   g_CT);
    float* d_W12;  cudaGetSymbolAddress((void**)&d_W12,  g_W12);

    // 1) tf32 conversions (no transposes needed for row.col WMMA)
    cvt_kernel<<<(MROWS * DIM / 4) / 256, 256>>>(x, d_xtf);
    cvt_kernel<<<(DIM * DIM / 4) / 256, 256>>>(Wq, d_Wtf);
    cvt_kernel<<<(DIM * DIM / 4) / 256, 256>>>(Wk, d_Wtf + (size_t)DIM * DIM);
    cvt_kernel<<<(DIM * DIM / 4) / 256, 256>>>(Wv, d_Wtf + (size_t)2 * DIM * DIM);

    // 2) dw^T (transpose + exp + tf32)
    dwA_kernel<<<dim3(SEQ / 32, SEQ / 32, BATCH), dim3(32, 8)>>>(dis, alpha);

    // 3) projections: Y[m][o] = sum_k x[m][k] * W[o][k]   (M=16384, N=1536, K=512)
    wmma_gemm_kernel<<<dim3(NPROJ / BN, MROWS / BM, 1), 256, SMEM_BYTES>>>(
        d_xtf, d_Wtf, d_Y, DIM, DIM, NPROJ, DIM, 0, 0, 0);

    // 4) CT tiles (interleaved exp(k)*v / exp(k), tf32)
    cT_kernel<<<dim3(SEQ / 32, DIM / 64, BATCH), 256>>>();

    // 5) main batched GEMM: W12[b][j][n] = sum_i dwA[b][j][i] * CT[b][n][i]
    wmma_gemm_kernel<<<dim3(N2 / BN, SEQ / BM, BATCH), 256, SMEM_BYTES>>>(
        d_dwA, d_CT, d_W12, SEQ, SEQ, N2, SEQ,
        (size_t)SEQ * SEQ, (size_t)N2 * SEQ, (size_t)SEQ * N2);

    // 6) fused sigmoid(q) * w1/w2 epilogue
    epilogue_kernel<<<(MROWS * DIM / 4) / 256, 256>>>(out);
}

// round 11
// speedup vs baseline: 1.3632x; 1.0004x over previous
#include <cuda_runtime.h>
#include <mma.h>
#include <cstdint>

using namespace nvcuda;

// Problem constants
#define BATCH 8
#define SEQ   2048
#define DIM   512
#define MROWS (BATCH*SEQ)   // 16384
#define NPROJ (3*DIM)       // 1536
#define N2    1024          // interleaved (w1,w2) feature dim

// WMMA GEMM tiling: 128x256 block, 64x64 warp (8 warps = 2x4)
#define BM 128
#define BN 256
#define BK 32
#define LDS_PAD 36                           // 32 + 4 floats per row
#define A_TILE_FLOATS (BM*LDS_PAD)           // 4608
#define B_TILE_FLOATS (BN*LDS_PAD)           // 9216
#define SMEM_BYTES ((2*A_TILE_FLOATS + 2*B_TILE_FLOATS)*4)  // 110592

// Scratch (static device globals — no allocation allowed)
__device__ __align__(16) float g_xtf [(size_t)MROWS * DIM];     // x as tf32
__device__ __align__(16) float g_Wtf [(size_t)NPROJ * DIM];     // [Wq;Wk;Wv] as tf32
__device__ __align__(16) float g_Y   [(size_t)MROWS * NPROJ];   // q|k|v projections (fp32)
__device__ __align__(16) float g_dwA [(size_t)BATCH * SEQ * SEQ];   // dw^T as tf32 [b][j][i]
__device__ __align__(16) float g_CT  [(size_t)BATCH * N2 * SEQ];    // [b][n][i] tf32
__device__ __align__(16) float g_W12 [(size_t)MROWS * N2];      // GEMM result (fp32)

// ---------------------------------------------------------------------------
// helpers
// ---------------------------------------------------------------------------
__device__ __forceinline__ uint32_t smem_u32(const void* p) {
    uint32_t a;
    asm("{ .reg .u64 t; cvta.to.shared.u64 t, %1; cvt.u32.u64 %0, t; }" : "=r"(a) : "l"(p));
    return a;
}
__device__ __forceinline__ float to_tf32f(float x) {
    uint32_t u; asm("cvt.rna.tf32.f32 %0, %1;" : "=r"(u) : "f"(x));
    return __uint_as_float(u);
}
__device__ __forceinline__ void cp16(float* dst_smem, const float* src) {
    uint32_t d = smem_u32(dst_smem);
    asm volatile("cp.async.cg.shared.global [%0], [%1], 16;" :: "r"(d), "l"(src));
}
#define CP_COMMIT() asm volatile("cp.async.commit_group;" ::: "memory")
#define CP_WAIT(n)  asm volatile("cp.async.wait_group %0;" :: "n"(n) : "memory")

// ---------------------------------------------------------------------------
// tf32 convert-copy (elementwise, float4)
// ---------------------------------------------------------------------------
__global__ void cvt_kernel(const float* __restrict__ in, float* __restrict__ out) {
    size_t i = (size_t)blockIdx.x * blockDim.x + threadIdx.x;
    float4 v = ((const float4*)in)[i];
    float4 o;
    o.x = to_tf32f(v.x); o.y = to_tf32f(v.y);
    o.z = to_tf32f(v.z); o.w = to_tf32f(v.w);
    ((float4*)out)[i] = o;
}

// ---------------------------------------------------------------------------
// dwA[b][j][i] = tf32(exp(-alpha*11*dis[b][i][j]))  — transpose + exp
// grid (64, 64, 8), block (32, 8)
// ---------------------------------------------------------------------------
__global__ void dwA_kernel(const float* __restrict__ dis, const float* __restrict__ alpha) {
    __shared__ float tile[32][33];
    int i0 = blockIdx.x * 32, j0 = blockIdx.y * 32, b = blockIdx.z;
    float c = -alpha[0] * 11.0f;   // log2(2048) = 11 exactly
    const float* src = dis + ((size_t)b * SEQ + i0) * SEQ + j0;
    #pragma unroll
    for (int rr = threadIdx.y; rr < 32; rr += 8)
        tile[rr][threadIdx.x] = __expf(c * src[(size_t)rr * SEQ + threadIdx.x]);
    __syncthreads();
    float* dst = g_dwA + ((size_t)b * SEQ + j0) * SEQ + i0;
    #pragma unroll
    for (int rr = threadIdx.y; rr < 32; rr += 8)
        dst[(size_t)rr * SEQ + threadIdx.x] = to_tf32f(tile[threadIdx.x][rr]);
}

// ---------------------------------------------------------------------------
// CT[b][n][i]: n=2d -> tf32(exp(k)*v), n=2d+1 -> tf32(exp(k))
// block covers 32 i x 64 d  ->  128 n-rows x 32 i.  grid (64, 8, 8), 256 thr
// ---------------------------------------------------------------------------
__global__ void cT_kernel() {
    __shared__ float ks[32][65];   // exp(k)
    __shared__ float vs[32][65];
    int i0 = blockIdx.x * 32, d0 = blockIdx.y * 64, b = blockIdx.z;
    int tid = threadIdx.x;
    #pragma unroll
    for (int u = tid; u < 32 * 64; u += 256) {
        int ii = u >> 6, dd = u & 63;
        const float* yrow = g_Y + ((size_t)b * SEQ + i0 + ii) * NPROJ;
        ks[ii][dd] = __expf(yrow[DIM + d0 + dd]);
        vs[ii][dd] = yrow[2 * DIM + d0 + dd];
    }
    __syncthreads();
    #pragma unroll
    for (int u = tid; u < 128 * 8; u += 256) {
        int n = u >> 3, i4 = (u & 7) * 4;
        int d = n >> 1, p = n & 1;
        float4 o;
        float k0 = ks[i4+0][d], k1 = ks[i4+1][d], k2 = ks[i4+2][d], k3 = ks[i4+3][d];
        if (p) {
            o.x = to_tf32f(k0); o.y = to_tf32f(k1); o.z = to_tf32f(k2); o.w = to_tf32f(k3);
        } else {
            o.x = to_tf32f(k0 * vs[i4+0][d]); o.y = to_tf32f(k1 * vs[i4+1][d]);
            o.z = to_tf32f(k2 * vs[i4+2][d]); o.w = to_tf32f(k3 * vs[i4+3][d]);
        }
        *(float4*)&g_CT[((size_t)b * N2 + d0 * 2 + n) * SEQ + i0 + i4] = o;
    }
}

// ---------------------------------------------------------------------------
// WMMA tf32 GEMM (row.col): C[m][n] = sum_k A[m][k] * B[n][k]
// 128x256 block tile, 64x64 warp tile, cp.async double-buffered, 256 threads
// ---------------------------------------------------------------------------
__global__ void __launch_bounds__(256, 1)
wmma_gemm_kernel(const float* __restrict__ A, const float* __restrict__ B,
                 float* __restrict__ C, int lda, int ldb, int ldc, int K,
                 size_t sA, size_t sB, size_t sC) {
    extern __shared__ float smem[];
    float* As = smem;                         // 2 stages x 4608
    float* Bs = smem + 2 * A_TILE_FLOATS;     // 2 stages x 9216

    A += (size_t)blockIdx.z * sA;
    B += (size_t)blockIdx.z * sB;
    C += (size_t)blockIdx.z * sC;

    int m0 = blockIdx.y * BM, n0 = blockIdx.x * BN;
    int tid = threadIdx.x;
    int wid = tid >> 5;
    int warp_m = wid & 1;    // 2 along M (64 rows each)
    int warp_n = wid >> 1;   // 4 along N (64 cols each)

    wmma::fragment<wmma::accumulator, 16, 16, 8, float> c[4][4];
    #pragma unroll
    for (int mi = 0; mi < 4; mi++)
        #pragma unroll
        for (int ni = 0; ni < 4; ni++) wmma::fill_fragment(c[mi][ni], 0.0f);

    const int KT = K / BK;

    auto load_stage = [&](int kt, int s) {
        const float* Ag = A + (size_t)m0 * lda + kt * BK;
        const float* Bg = B + (size_t)n0 * ldb + kt * BK;
        float* Ad = As + s * A_TILE_FLOATS;
        float* Bd = Bs + s * B_TILE_FLOATS;
        #pragma unroll
        for (int it = 0; it < 4; it++) {           // A: 128 rows x 8 float4
            int idx = tid + it * 256;
            int row = idx >> 3, c4 = (idx & 7) * 4;
            cp16(Ad + row * LDS_PAD + c4, Ag + (size_t)row * lda + c4);
        }
        #pragma unroll
        for (int it = 0; it < 8; it++) {           // B: 256 rows x 8 float4
            int idx = tid + it * 256;
            int row = idx >> 3, c4 = (idx & 7) * 4;
            cp16(Bd + row * LDS_PAD + c4, Bg + (size_t)row * ldb + c4);
        }
    };

    load_stage(0, 0);
    CP_COMMIT();

    for (int kt = 0; kt < KT; kt++) {
        int s = kt & 1;
        if (kt + 1 < KT) {
            load_stage(kt + 1, s ^ 1);
            CP_COMMIT();
            CP_WAIT(1);
        } else {
            CP_WAIT(0);
        }
        __syncthreads();

        const float* Abase = As + s * A_TILE_FLOATS + (warp_m * 64) * LDS_PAD;
        const float* Bbase = Bs + s * B_TILE_FLOATS + (warp_n * 64) * LDS_PAD;
        #pragma unroll
        for (int ks = 0; ks < BK / 8; ks++) {
            wmma::fragment<wmma::matrix_a, 16, 16, 8, wmma::precision::tf32, wmma::row_major> a[4];
            wmma::fragment<wmma::matrix_b, 16, 16, 8, wmma::precision::tf32, wmma::col_major> bfr[4];
            #pragma unroll
            for (int mi = 0; mi < 4; mi++)
                wmma::load_matrix_sync(a[mi], Abase + mi * 16 * LDS_PAD + ks * 8, LDS_PAD);
            #pragma unroll
            for (int ni = 0; ni < 4; ni++)
                wmma::load_matrix_sync(bfr[ni], Bbase + ni * 16 * LDS_PAD + ks * 8, LDS_PAD);
            #pragma unroll
            for (int mi = 0; mi < 4; mi++)
                #pragma unroll
                for (int ni = 0; ni < 4; ni++)
                    wmma::mma_sync(c[mi][ni], a[mi], bfr[ni], c[mi][ni]);
        }
        __syncthreads();
    }

    #pragma unroll
    for (int mi = 0; mi < 4; mi++)
        #pragma unroll
        for (int ni = 0; ni < 4; ni++) {
            int m = m0 + warp_m * 64 + mi * 16;
            int n = n0 + warp_n * 64 + ni * 16;
            wmma::store_matrix_sync(C + (size_t)m * ldc + n, c[mi][ni], ldc, wmma::mem_row_major);
        }
}

// ---------------------------------------------------------------------------
// Epilogue: out[row][d] = sigmoid(q[row][d]) * W12[row][2d] / W12[row][2d+1]
// ---------------------------------------------------------------------------
__global__ void epilogue_kernel(float* __restrict__ out) {
    size_t idx = (size_t)blockIdx.x * blockDim.x + threadIdx.x;
    int row = (int)(idx >> 7);          // 128 float4 per row
    int d0  = (int)(idx & 127) * 4;
    const float* qp = g_Y + (size_t)row * NPROJ + d0;
    const float* wp = g_W12 + (size_t)row * N2 + 2 * d0;
    float4 q  = *(const float4*)qp;
    float4 wa = *(const float4*)(wp);
    float4 wb = *(const float4*)(wp + 4);
    float4 o;
    o.x = __fdividef(1.f, 1.f + __expf(-q.x)) * __fdividef(wa.x, wa.y);
    o.y = __fdividef(1.f, 1.f + __expf(-q.y)) * __fdividef(wa.z, wa.w);
    o.z = __fdividef(1.f, 1.f + __expf(-q.z)) * __fdividef(wb.x, wb.y);
    o.w = __fdividef(1.f, 1.f + __expf(-q.w)) * __fdividef(wb.z, wb.w);
    *(float4*)(out + (size_t)row * DIM + d0) = o;
}

// ---------------------------------------------------------------------------
extern "C" void kernel_launch(void* const* d_in, const int* in_sizes, int n_in,
                              void* d_out, int out_size) {
    const float* x     = (const float*)d_in[0];
    const float* dis   = (const float*)d_in[1];
    const float* Wq    = (const float*)d_in[2];
    const float* Wk    = (const float*)d_in[3];
    const float* Wv    = (const float*)d_in[4];
    const float* alpha = (const float*)d_in[5];
    float* out = (float*)d_out;

    cudaFuncSetAttribute(wmma_gemm_kernel, cudaFuncAttributeMaxDynamicSharedMemorySize, SMEM_BYTES);

    float* d_xtf;  cudaGetSymbolAddress((void**)&d_xtf,  g_xtf);
    float* d_Wtf;  cudaGetSymbolAddress((void**)&d_Wtf,  g_Wtf);
    float* d_Y;    cudaGetSymbolAddress((void**)&d_Y,    g_Y);
    float* d_dwA;  cudaGetSymbolAddress((void**)&d_dwA,  g_dwA);
    float* d_CT;   cudaGetSymbolAddress((void**)&d_CT,   g_CT);
    float* d_W12;  cudaGetSymbolAddress((void**)&d_W12,  g_W12);

    // 1) tf32 conversions
    cvt_kernel<<<(MROWS * DIM / 4) / 256, 256>>>(x, d_xtf);
    cvt_kernel<<<(DIM * DIM / 4) / 256, 256>>>(Wq, d_Wtf);
    cvt_kernel<<<(DIM * DIM / 4) / 256, 256>>>(Wk, d_Wtf + (size_t)DIM * DIM);
    cvt_kernel<<<(DIM * DIM / 4) / 256, 256>>>(Wv, d_Wtf + (size_t)2 * DIM * DIM);

    // 2) dw^T (transpose + exp + tf32)
    dwA_kernel<<<dim3(SEQ / 32, SEQ / 32, BATCH), dim3(32, 8)>>>(dis, alpha);

    // 3) projections: Y[m][o] = sum_k x[m][k] * W[o][k]   (M=16384, N=1536, K=512)
    wmma_gemm_kernel<<<dim3(NPROJ / BN, MROWS / BM, 1), 256, SMEM_BYTES>>>(
        d_xtf, d_Wtf, d_Y, DIM, DIM, NPROJ, DIM, 0, 0, 0);

    // 4) CT tiles
    cT_kernel<<<dim3(SEQ / 32, DIM / 64, BATCH), 256>>>();

    // 5) main batched GEMM: W12[b][j][n] = sum_i dwA[b][j][i] * CT[b][n][i]
    wmma_gemm_kernel<<<dim3(N2 / BN, SEQ / BM, BATCH), 256, SMEM_BYTES>>>(
        d_dwA, d_CT, d_W12, SEQ, SEQ, N2, SEQ,
        (size_t)SEQ * SEQ, (size_t)N2 * SEQ, (size_t)SEQ * N2);

    // 6) fused sigmoid(q) * w1/w2 epilogue
    epilogue_kernel<<<(MROWS * DIM / 4) / 256, 256>>>(out);
}